// round 2
// baseline (speedup 1.0000x reference)
#include <cuda_runtime.h>
#include <math.h>
#include <stdint.h>

// Problem constants
#define B_    8
#define NE    4
#define Tn    1024
#define D_    1024
#define G_    8
#define BLK   128
#define TT    64
#define DLLM  2048
#define NT    (B_*NE*Tn)          // 32768 tokens
#define SCALEF 0.08838834764831845f  // 128^-0.5

// -------- device scratch (no dynamic allocation allowed) --------
__device__ float g_kvp[16*2*8*64*128];   // K-split partials for k/v
__device__ float g_k[B_*TT*BLK];         // [8][64][128]
__device__ float g_v[B_*TT*BLK];
__device__ float g_A[NT*BLK];            // gate*gamma
__device__ float g_B[NT*BLK];            // gate*beta

// ============================================================================
// Kernel 1: k/v projection, split-K GEMM.
// ============================================================================
__global__ void kv_kernel(const float* __restrict__ h_llm,
                          const float* __restrict__ Wk,
                          const float* __restrict__ Wv) {
    extern __shared__ float sm[];
    float* ws = sm;              // [64][132]  = 8448 floats
    float* xs = sm + 64*132;     // [64][64]   = 4096 floats
    int bx = blockIdx.x;
    int slice = bx >> 4;
    int b     = (bx >> 1) & 7;
    int which = bx & 1;
    const float* W = which ? Wv : Wk;
    int kbase = slice * 128;
    int tid = threadIdx.x;
    int oq = tid & 31, sg = tid >> 5;
    int o0 = oq * 4;

    float acc[8][4];
    #pragma unroll
    for (int r = 0; r < 8; r++)
        #pragma unroll
        for (int j = 0; j < 4; j++) acc[r][j] = 0.f;

    for (int kc = 0; kc < 128; kc += 64) {
        __syncthreads();
        for (int idx = tid; idx < 64*64; idx += 256) {
            int s = idx >> 6, i = idx & 63;
            xs[s*64 + i] = h_llm[(size_t)b*TT*DLLM + (size_t)s*DLLM + kbase + kc + i];
        }
        for (int idx = tid; idx < 128*64; idx += 256) {
            int o = idx >> 6, i = idx & 63;
            ws[i*132 + o] = W[(size_t)o*DLLM + kbase + kc + i];
        }
        __syncthreads();
        for (int i = 0; i < 64; i++) {
            float4 w4 = *(const float4*)&ws[i*132 + o0];
            #pragma unroll
            for (int r = 0; r < 8; r++) {
                float x = xs[(sg*8 + r)*64 + i];
                acc[r][0] += x * w4.x; acc[r][1] += x * w4.y;
                acc[r][2] += x * w4.z; acc[r][3] += x * w4.w;
            }
        }
    }
    float* outp = g_kvp + ((size_t)(slice*2 + which)*8 + b) * (64*128);
    #pragma unroll
    for (int r = 0; r < 8; r++) {
        int s = sg*8 + r;
        float4 v4 = make_float4(acc[r][0], acc[r][1], acc[r][2], acc[r][3]);
        *(float4*)&outp[s*128 + o0] = v4;
    }
}

// Reduce the 16 K-slices + bias -> g_k / g_v.
__global__ void kv_reduce(const float* __restrict__ bk,
                          const float* __restrict__ bv) {
    int idx = blockIdx.x * 256 + threadIdx.x;
    if (idx >= 2*8*64*128) return;
    int which = idx >> 16;
    int rem   = idx & 65535;
    int o = rem & 127;
    float s = which ? bv[o] : bk[o];
    #pragma unroll
    for (int sl = 0; sl < 16; sl++)
        s += g_kvp[(size_t)(sl*2 + which)*65536 + rem];
    (which ? g_v : g_k)[rem] = s;
}

// ============================================================================
// Kernel 2: "mega" — attention path producing g_A = gate*gamma, g_B = gate*beta.
// ============================================================================
#define MEGA_SMEM ((16896 + 8192 + 4160 + 8704) * 4)

__global__ void mega_kernel(const float* __restrict__ h_prime,
                            const float* __restrict__ Wq, const float* __restrict__ bq,
                            const float* __restrict__ Wg, const float* __restrict__ bg,
                            const float* __restrict__ Wb, const float* __restrict__ bb) {
    extern __shared__ float sm[];
    float* ws = sm;
    float* xs = sm + 16896;
    float* ss = xs + 8192;
    float* qs = ss + 4160;

    int tid = threadIdx.x;
    int t0  = blockIdx.x * 64;
    int b   = t0 >> 12;
    int oq  = tid & 31, tg = tid >> 5;
    int o0  = oq * 4;

    // inv = max over groups; WqT into ws
    for (int idx = tid; idx < 8192; idx += 256) {
        int t = idx >> 7, j = idx & 127;
        const float* hp = h_prime + (size_t)(t0 + t)*1024 + j;
        float m = hp[0];
        #pragma unroll
        for (int g = 1; g < 8; g++) m = fmaxf(m, hp[g*128]);
        xs[idx] = m;
    }
    for (int idx = tid; idx < 16384; idx += 256) {
        int o = idx >> 7, i = idx & 127;
        ws[i*132 + o] = Wq[idx];
    }
    __syncthreads();

    // q = inv @ WqT + bq, pre-scaled, into qs[d][t]
    {
        float acc[8][4];
        #pragma unroll
        for (int r = 0; r < 8; r++)
            #pragma unroll
            for (int j = 0; j < 4; j++) acc[r][j] = 0.f;
        for (int i = 0; i < 128; i++) {
            float4 w4 = *(const float4*)&ws[i*132 + o0];
            #pragma unroll
            for (int r = 0; r < 8; r++) {
                float x = xs[(tg*8 + r)*128 + i];
                acc[r][0] += x * w4.x; acc[r][1] += x * w4.y;
                acc[r][2] += x * w4.z; acc[r][3] += x * w4.w;
            }
        }
        float4 bq4 = *(const float4*)&bq[o0];
        #pragma unroll
        for (int r = 0; r < 8; r++) {
            int t = tg*8 + r;
            qs[(o0+0)*68 + t] = (acc[r][0] + bq4.x) * SCALEF;
            qs[(o0+1)*68 + t] = (acc[r][1] + bq4.y) * SCALEF;
            qs[(o0+2)*68 + t] = (acc[r][2] + bq4.z) * SCALEF;
            qs[(o0+3)*68 + t] = (acc[r][3] + bq4.w) * SCALEF;
        }
    }
    __syncthreads();

    // load k (transposed) + v for this batch
    for (int idx = tid; idx < 8192; idx += 256) {
        int s = idx >> 7, d = idx & 127;
        float kvval = g_k[(size_t)b*8192 + idx];
        ws[d*68 + s]  = kvval;
        ws[8704 + idx] = g_v[(size_t)b*8192 + idx];
    }
    __syncthreads();

    // scores
    {
        int t4 = tid & 15, s4 = tid >> 4;
        int tt0 = t4*4, s0 = s4*4;
        float acc[4][4];
        #pragma unroll
        for (int a = 0; a < 4; a++)
            #pragma unroll
            for (int c = 0; c < 4; c++) acc[a][c] = 0.f;
        for (int d = 0; d < 128; d++) {
            float4 q4 = *(const float4*)&qs[d*68 + tt0];
            float4 k4 = *(const float4*)&ws[d*68 + s0];
            acc[0][0]+=q4.x*k4.x; acc[0][1]+=q4.x*k4.y; acc[0][2]+=q4.x*k4.z; acc[0][3]+=q4.x*k4.w;
            acc[1][0]+=q4.y*k4.x; acc[1][1]+=q4.y*k4.y; acc[1][2]+=q4.y*k4.z; acc[1][3]+=q4.y*k4.w;
            acc[2][0]+=q4.z*k4.x; acc[2][1]+=q4.z*k4.y; acc[2][2]+=q4.z*k4.z; acc[2][3]+=q4.z*k4.w;
            acc[3][0]+=q4.w*k4.x; acc[3][1]+=q4.w*k4.y; acc[3][2]+=q4.w*k4.z; acc[3][3]+=q4.w*k4.w;
        }
        #pragma unroll
        for (int a = 0; a < 4; a++)
            #pragma unroll
            for (int c = 0; c < 4; c++)
                ss[(tt0 + a)*65 + s0 + c] = acc[a][c];
    }
    __syncthreads();

    // softmax
    if (tid < 64) {
        float* row = ss + tid*65;
        float m = row[0];
        for (int s = 1; s < 64; s++) m = fmaxf(m, row[s]);
        float sum = 0.f;
        for (int s = 0; s < 64; s++) { float e = __expf(row[s] - m); row[s] = e; sum += e; }
        float inv = 1.f / sum;
        for (int s = 0; s < 64; s++) row[s] *= inv;
    }
    __syncthreads();

    // ctx = attn @ v
    {
        const float* vs = ws + 8704;
        float acc[8][4];
        #pragma unroll
        for (int r = 0; r < 8; r++)
            #pragma unroll
            for (int j = 0; j < 4; j++) acc[r][j] = 0.f;
        for (int s = 0; s < 64; s++) {
            float4 v4 = *(const float4*)&vs[s*128 + o0];
            #pragma unroll
            for (int r = 0; r < 8; r++) {
                float p = ss[(tg*8 + r)*65 + s];
                acc[r][0] += p * v4.x; acc[r][1] += p * v4.y;
                acc[r][2] += p * v4.z; acc[r][3] += p * v4.w;
            }
        }
        #pragma unroll
        for (int r = 0; r < 8; r++) {
            int t = tg*8 + r;
            xs[t*128 + o0 + 0] = acc[r][0];
            xs[t*128 + o0 + 1] = acc[r][1];
            xs[t*128 + o0 + 2] = acc[r][2];
            xs[t*128 + o0 + 3] = acc[r][3];
        }
    }
    __syncthreads();

    // A = sigmoid(ctx) * (ctx @ WgT + bg)
    for (int idx = tid; idx < 16384; idx += 256) {
        int o = idx >> 7, i = idx & 127;
        ws[i*132 + o] = Wg[idx];
    }
    __syncthreads();
    {
        float acc[8][4];
        #pragma unroll
        for (int r = 0; r < 8; r++)
            #pragma unroll
            for (int j = 0; j < 4; j++) acc[r][j] = 0.f;
        for (int i = 0; i < 128; i++) {
            float4 w4 = *(const float4*)&ws[i*132 + o0];
            #pragma unroll
            for (int r = 0; r < 8; r++) {
                float x = xs[(tg*8 + r)*128 + i];
                acc[r][0] += x * w4.x; acc[r][1] += x * w4.y;
                acc[r][2] += x * w4.z; acc[r][3] += x * w4.w;
            }
        }
        float4 bg4 = *(const float4*)&bg[o0];
        #pragma unroll
        for (int r = 0; r < 8; r++) {
            int t = tg*8 + r;
            float4 c4 = *(const float4*)&xs[t*128 + o0];
            float4 res;
            res.x = (1.f/(1.f+__expf(-c4.x))) * (acc[r][0] + bg4.x);
            res.y = (1.f/(1.f+__expf(-c4.y))) * (acc[r][1] + bg4.y);
            res.z = (1.f/(1.f+__expf(-c4.z))) * (acc[r][2] + bg4.z);
            res.w = (1.f/(1.f+__expf(-c4.w))) * (acc[r][3] + bg4.w);
            *(float4*)&g_A[(size_t)(t0 + t)*128 + o0] = res;
        }
    }
    __syncthreads();

    // B = sigmoid(ctx) * (ctx @ WbT + bb)
    for (int idx = tid; idx < 16384; idx += 256) {
        int o = idx >> 7, i = idx & 127;
        ws[i*132 + o] = Wb[idx];
    }
    __syncthreads();
    {
        float acc[8][4];
        #pragma unroll
        for (int r = 0; r < 8; r++)
            #pragma unroll
            for (int j = 0; j < 4; j++) acc[r][j] = 0.f;
        for (int i = 0; i < 128; i++) {
            float4 w4 = *(const float4*)&ws[i*132 + o0];
            #pragma unroll
            for (int r = 0; r < 8; r++) {
                float x = xs[(tg*8 + r)*128 + i];
                acc[r][0] += x * w4.x; acc[r][1] += x * w4.y;
                acc[r][2] += x * w4.z; acc[r][3] += x * w4.w;
            }
        }
        float4 bb4 = *(const float4*)&bb[o0];
        #pragma unroll
        for (int r = 0; r < 8; r++) {
            int t = tg*8 + r;
            float4 c4 = *(const float4*)&xs[t*128 + o0];
            float4 res;
            res.x = (1.f/(1.f+__expf(-c4.x))) * (acc[r][0] + bb4.x);
            res.y = (1.f/(1.f+__expf(-c4.y))) * (acc[r][1] + bb4.y);
            res.z = (1.f/(1.f+__expf(-c4.z))) * (acc[r][2] + bb4.z);
            res.w = (1.f/(1.f+__expf(-c4.w))) * (acc[r][3] + bb4.w);
            *(float4*)&g_B[(size_t)(t0 + t)*128 + o0] = res;
        }
    }
}

// ============================================================================
// Kernel 3: final — equi GEMM on tf32 tensor cores (mma.sync.m16n8k8) fused
// with FiLM + residual.
//   A = h_prime as [262144 x 128] row-major (rows = (token,group) slices)
//   B(k,n) = We[n][k]  (We row-major == B col-major)
// CTA: 128 rows x 128 cols, 8 warps (4x2), warp = 32 rows x 64 cols.
// smem: A tile [128][132] tf32 + We [128][132] tf32 = 135168 B.
// Epilogue: out = h + g_A*D + g_B  (h re-read from gmem, L2-hot).
// ============================================================================
#define FK_SMEM (2 * 128 * 132 * 4)

__device__ __forceinline__ uint32_t f2tf32(float x) {
    uint32_t u;
    asm("cvt.rna.tf32.f32 %0, %1;" : "=r"(u) : "f"(x));
    return u;
}

__global__ void __launch_bounds__(256)
final_kernel(const float* __restrict__ h_prime,
             const float* __restrict__ We,
             const float* __restrict__ gA,
             const float* __restrict__ gB,
             float* __restrict__ out) {
    extern __shared__ uint32_t smu[];
    uint32_t* as = smu;               // A tile [128][132]
    uint32_t* ws = smu + 128*132;     // We     [128][132]

    int tid = threadIdx.x;
    size_t base = (size_t)blockIdx.x * 128;     // first global row of this CTA

    // ---- stage A tile (contiguous 64KB span) + We, rounding to tf32 ----
    const float4* asrc = (const float4*)(h_prime + base*128);
    for (int i4 = tid; i4 < 4096; i4 += 256) {
        float4 v = asrc[i4];
        int idx = i4 * 4;
        int r = idx >> 7, k = idx & 127;
        uint32_t* p = &as[r*132 + k];
        p[0] = f2tf32(v.x); p[1] = f2tf32(v.y); p[2] = f2tf32(v.z); p[3] = f2tf32(v.w);
    }
    const float4* wsrc = (const float4*)We;
    for (int i4 = tid; i4 < 4096; i4 += 256) {
        float4 v = wsrc[i4];
        int idx = i4 * 4;
        int r = idx >> 7, k = idx & 127;
        uint32_t* p = &ws[r*132 + k];
        p[0] = f2tf32(v.x); p[1] = f2tf32(v.y); p[2] = f2tf32(v.z); p[3] = f2tf32(v.w);
    }
    __syncthreads();

    int w    = tid >> 5;
    int lane = tid & 31;
    int gid  = lane >> 2;      // group-of-4 id (0..7)
    int ctg  = lane & 3;       // thread in group (0..3)
    int row0 = (w & 3) * 32;
    int col0 = (w >> 2) * 64;

    float acc[2][8][4];
    #pragma unroll
    for (int mi = 0; mi < 2; mi++)
        #pragma unroll
        for (int ni = 0; ni < 8; ni++)
            #pragma unroll
            for (int j = 0; j < 4; j++) acc[mi][ni][j] = 0.f;

    // ---- mainloop: 16 k-steps of 8 ----
    #pragma unroll 4
    for (int ks = 0; ks < 16; ks++) {
        int k0 = ks * 8;
        uint32_t a[2][4];
        #pragma unroll
        for (int mi = 0; mi < 2; mi++) {
            int rbase = (row0 + mi*16 + gid) * 132;
            a[mi][0] = as[rbase + k0 + ctg];
            a[mi][1] = as[rbase + 8*132 + k0 + ctg];
            a[mi][2] = as[rbase + k0 + ctg + 4];
            a[mi][3] = as[rbase + 8*132 + k0 + ctg + 4];
        }
        #pragma unroll
        for (int ni = 0; ni < 8; ni++) {
            int nbase = (col0 + ni*8 + gid) * 132;
            uint32_t b0 = ws[nbase + k0 + ctg];
            uint32_t b1 = ws[nbase + k0 + ctg + 4];
            #pragma unroll
            for (int mi = 0; mi < 2; mi++) {
                asm volatile(
                    "mma.sync.aligned.m16n8k8.row.col.f32.tf32.tf32.f32 "
                    "{%0,%1,%2,%3}, {%4,%5,%6,%7}, {%8,%9}, {%0,%1,%2,%3};"
                    : "+f"(acc[mi][ni][0]), "+f"(acc[mi][ni][1]),
                      "+f"(acc[mi][ni][2]), "+f"(acc[mi][ni][3])
                    : "r"(a[mi][0]), "r"(a[mi][1]), "r"(a[mi][2]), "r"(a[mi][3]),
                      "r"(b0), "r"(b1));
            }
        }
    }

    // ---- epilogue: out = h + gA*D + gB ----
    #pragma unroll
    for (int mi = 0; mi < 2; mi++) {
        #pragma unroll
        for (int ni = 0; ni < 8; ni++) {
            int c = col0 + ni*8 + ctg*2;
            // low rows (c0,c1)
            {
                size_t R = base + row0 + mi*16 + gid;
                size_t t = R >> 3;
                float2 h2 = *(const float2*)&h_prime[R*128 + c];
                float2 A2 = *(const float2*)&gA[t*128 + c];
                float2 B2 = *(const float2*)&gB[t*128 + c];
                float2 r2;
                r2.x = h2.x + A2.x * acc[mi][ni][0] + B2.x;
                r2.y = h2.y + A2.y * acc[mi][ni][1] + B2.y;
                *(float2*)&out[R*128 + c] = r2;
            }
            // high rows (c2,c3)
            {
                size_t R = base + row0 + mi*16 + gid + 8;
                size_t t = R >> 3;
                float2 h2 = *(const float2*)&h_prime[R*128 + c];
                float2 A2 = *(const float2*)&gA[t*128 + c];
                float2 B2 = *(const float2*)&gB[t*128 + c];
                float2 r2;
                r2.x = h2.x + A2.x * acc[mi][ni][2] + B2.x;
                r2.y = h2.y + A2.y * acc[mi][ni][3] + B2.y;
                *(float2*)&out[R*128 + c] = r2;
            }
        }
    }
}

// ============================================================================
extern "C" void kernel_launch(void* const* d_in, const int* in_sizes, int n_in,
                              void* d_out, int out_size) {
    const float* h_prime = (const float*)d_in[0];
    const float* h_llm   = (const float*)d_in[1];
    const float* Wq = (const float*)d_in[2];
    const float* bq = (const float*)d_in[3];
    const float* Wk = (const float*)d_in[4];
    const float* bk = (const float*)d_in[5];
    const float* Wv = (const float*)d_in[6];
    const float* bv = (const float*)d_in[7];
    const float* Wg = (const float*)d_in[8];
    const float* bg = (const float*)d_in[9];
    const float* Wb = (const float*)d_in[10];
    const float* bb = (const float*)d_in[11];
    const float* We = (const float*)d_in[12];
    float* out = (float*)d_out;

    const int KV_SMEM = (8448 + 4096) * 4;
    cudaFuncSetAttribute(kv_kernel,    cudaFuncAttributeMaxDynamicSharedMemorySize, KV_SMEM);
    cudaFuncSetAttribute(mega_kernel,  cudaFuncAttributeMaxDynamicSharedMemorySize, MEGA_SMEM);
    cudaFuncSetAttribute(final_kernel, cudaFuncAttributeMaxDynamicSharedMemorySize, FK_SMEM);

    // pointers to device scratch for final kernel
    float *pA, *pB;
    cudaGetSymbolAddress((void**)&pA, g_A);
    cudaGetSymbolAddress((void**)&pB, g_B);

    kv_kernel<<<256, 256, KV_SMEM>>>(h_llm, Wk, Wv);
    kv_reduce<<<512, 256>>>(bk, bv);
    mega_kernel<<<512, 256, MEGA_SMEM>>>(h_prime, Wq, bq, Wg, bg, Wb, bb);
    final_kernel<<<2048, 256, FK_SMEM>>>(h_prime, We, pA, pB, out);
}

// round 4
// speedup vs baseline: 1.8858x; 1.8858x over previous
#include <cuda_runtime.h>
#include <math.h>
#include <stdint.h>

// Problem constants
#define B_    8
#define NE    4
#define Tn    1024
#define D_    1024
#define G_    8
#define BLK   128
#define TT    64
#define DLLM  2048
#define NT    (B_*NE*Tn)          // 32768 tokens
#define SCALEF 0.08838834764831845f  // 128^-0.5

// -------- device scratch (no dynamic allocation allowed) --------
__device__ float g_kvp[16*2*8*64*128];   // K-split partials for k/v
__device__ float g_k[B_*TT*BLK];         // [8][64][128]
__device__ float g_v[B_*TT*BLK];
__device__ float g_A[NT*BLK];            // gate*gamma
__device__ float g_B[NT*BLK];            // gate*beta

// ============================================================================
// Kernel 1: k/v projection, split-K GEMM.
// ============================================================================
__global__ void kv_kernel(const float* __restrict__ h_llm,
                          const float* __restrict__ Wk,
                          const float* __restrict__ Wv) {
    extern __shared__ float sm[];
    float* ws = sm;              // [64][132]
    float* xs = sm + 64*132;     // [64][64]
    int bx = blockIdx.x;
    int slice = bx >> 4;
    int b     = (bx >> 1) & 7;
    int which = bx & 1;
    const float* W = which ? Wv : Wk;
    int kbase = slice * 128;
    int tid = threadIdx.x;
    int oq = tid & 31, sg = tid >> 5;
    int o0 = oq * 4;

    float acc[8][4];
    #pragma unroll
    for (int r = 0; r < 8; r++)
        #pragma unroll
        for (int j = 0; j < 4; j++) acc[r][j] = 0.f;

    for (int kc = 0; kc < 128; kc += 64) {
        __syncthreads();
        for (int idx = tid; idx < 64*64; idx += 256) {
            int s = idx >> 6, i = idx & 63;
            xs[s*64 + i] = h_llm[(size_t)b*TT*DLLM + (size_t)s*DLLM + kbase + kc + i];
        }
        for (int idx = tid; idx < 128*64; idx += 256) {
            int o = idx >> 6, i = idx & 63;
            ws[i*132 + o] = W[(size_t)o*DLLM + kbase + kc + i];
        }
        __syncthreads();
        for (int i = 0; i < 64; i++) {
            float4 w4 = *(const float4*)&ws[i*132 + o0];
            #pragma unroll
            for (int r = 0; r < 8; r++) {
                float x = xs[(sg*8 + r)*64 + i];
                acc[r][0] += x * w4.x; acc[r][1] += x * w4.y;
                acc[r][2] += x * w4.z; acc[r][3] += x * w4.w;
            }
        }
    }
    float* outp = g_kvp + ((size_t)(slice*2 + which)*8 + b) * (64*128);
    #pragma unroll
    for (int r = 0; r < 8; r++) {
        int s = sg*8 + r;
        float4 v4 = make_float4(acc[r][0], acc[r][1], acc[r][2], acc[r][3]);
        *(float4*)&outp[s*128 + o0] = v4;
    }
}

// Reduce the 16 K-slices + bias -> g_k / g_v.
__global__ void kv_reduce(const float* __restrict__ bk,
                          const float* __restrict__ bv) {
    int idx = blockIdx.x * 256 + threadIdx.x;
    if (idx >= 2*8*64*128) return;
    int which = idx >> 16;
    int rem   = idx & 65535;
    int o = rem & 127;
    float s = which ? bv[o] : bk[o];
    #pragma unroll
    for (int sl = 0; sl < 16; sl++)
        s += g_kvp[(size_t)(sl*2 + which)*65536 + rem];
    (which ? g_v : g_k)[rem] = s;
}

// ============================================================================
// Kernel 2: "mega" — attention path producing g_A = gate*gamma, g_B = gate*beta.
// ============================================================================
#define MEGA_SMEM ((16896 + 8192 + 4160 + 8704) * 4)

__global__ void mega_kernel(const float* __restrict__ h_prime,
                            const float* __restrict__ Wq, const float* __restrict__ bq,
                            const float* __restrict__ Wg, const float* __restrict__ bg,
                            const float* __restrict__ Wb, const float* __restrict__ bb) {
    extern __shared__ float sm[];
    float* ws = sm;
    float* xs = sm + 16896;
    float* ss = xs + 8192;
    float* qs = ss + 4160;

    int tid = threadIdx.x;
    int t0  = blockIdx.x * 64;
    int b   = t0 >> 12;
    int oq  = tid & 31, tg = tid >> 5;
    int o0  = oq * 4;

    // inv = max over groups; WqT into ws
    for (int idx = tid; idx < 8192; idx += 256) {
        int t = idx >> 7, j = idx & 127;
        const float* hp = h_prime + (size_t)(t0 + t)*1024 + j;
        float m = hp[0];
        #pragma unroll
        for (int g = 1; g < 8; g++) m = fmaxf(m, hp[g*128]);
        xs[idx] = m;
    }
    for (int idx = tid; idx < 16384; idx += 256) {
        int o = idx >> 7, i = idx & 127;
        ws[i*132 + o] = Wq[idx];
    }
    __syncthreads();

    // q = inv @ WqT + bq, pre-scaled, into qs[d][t]
    {
        float acc[8][4];
        #pragma unroll
        for (int r = 0; r < 8; r++)
            #pragma unroll
            for (int j = 0; j < 4; j++) acc[r][j] = 0.f;
        for (int i = 0; i < 128; i++) {
            float4 w4 = *(const float4*)&ws[i*132 + o0];
            #pragma unroll
            for (int r = 0; r < 8; r++) {
                float x = xs[(tg*8 + r)*128 + i];
                acc[r][0] += x * w4.x; acc[r][1] += x * w4.y;
                acc[r][2] += x * w4.z; acc[r][3] += x * w4.w;
            }
        }
        float4 bq4 = *(const float4*)&bq[o0];
        #pragma unroll
        for (int r = 0; r < 8; r++) {
            int t = tg*8 + r;
            qs[(o0+0)*68 + t] = (acc[r][0] + bq4.x) * SCALEF;
            qs[(o0+1)*68 + t] = (acc[r][1] + bq4.y) * SCALEF;
            qs[(o0+2)*68 + t] = (acc[r][2] + bq4.z) * SCALEF;
            qs[(o0+3)*68 + t] = (acc[r][3] + bq4.w) * SCALEF;
        }
    }
    __syncthreads();

    // load k (transposed) + v for this batch
    for (int idx = tid; idx < 8192; idx += 256) {
        int s = idx >> 7, d = idx & 127;
        float kvval = g_k[(size_t)b*8192 + idx];
        ws[d*68 + s]  = kvval;
        ws[8704 + idx] = g_v[(size_t)b*8192 + idx];
    }
    __syncthreads();

    // scores
    {
        int t4 = tid & 15, s4 = tid >> 4;
        int tt0 = t4*4, s0 = s4*4;
        float acc[4][4];
        #pragma unroll
        for (int a = 0; a < 4; a++)
            #pragma unroll
            for (int c = 0; c < 4; c++) acc[a][c] = 0.f;
        for (int d = 0; d < 128; d++) {
            float4 q4 = *(const float4*)&qs[d*68 + tt0];
            float4 k4 = *(const float4*)&ws[d*68 + s0];
            acc[0][0]+=q4.x*k4.x; acc[0][1]+=q4.x*k4.y; acc[0][2]+=q4.x*k4.z; acc[0][3]+=q4.x*k4.w;
            acc[1][0]+=q4.y*k4.x; acc[1][1]+=q4.y*k4.y; acc[1][2]+=q4.y*k4.z; acc[1][3]+=q4.y*k4.w;
            acc[2][0]+=q4.z*k4.x; acc[2][1]+=q4.z*k4.y; acc[2][2]+=q4.z*k4.z; acc[2][3]+=q4.z*k4.w;
            acc[3][0]+=q4.w*k4.x; acc[3][1]+=q4.w*k4.y; acc[3][2]+=q4.w*k4.z; acc[3][3]+=q4.w*k4.w;
        }
        #pragma unroll
        for (int a = 0; a < 4; a++)
            #pragma unroll
            for (int c = 0; c < 4; c++)
                ss[(tt0 + a)*65 + s0 + c] = acc[a][c];
    }
    __syncthreads();

    // softmax
    if (tid < 64) {
        float* row = ss + tid*65;
        float m = row[0];
        for (int s = 1; s < 64; s++) m = fmaxf(m, row[s]);
        float sum = 0.f;
        for (int s = 0; s < 64; s++) { float e = __expf(row[s] - m); row[s] = e; sum += e; }
        float inv = 1.f / sum;
        for (int s = 0; s < 64; s++) row[s] *= inv;
    }
    __syncthreads();

    // ctx = attn @ v
    {
        const float* vs = ws + 8704;
        float acc[8][4];
        #pragma unroll
        for (int r = 0; r < 8; r++)
            #pragma unroll
            for (int j = 0; j < 4; j++) acc[r][j] = 0.f;
        for (int s = 0; s < 64; s++) {
            float4 v4 = *(const float4*)&vs[s*128 + o0];
            #pragma unroll
            for (int r = 0; r < 8; r++) {
                float p = ss[(tg*8 + r)*65 + s];
                acc[r][0] += p * v4.x; acc[r][1] += p * v4.y;
                acc[r][2] += p * v4.z; acc[r][3] += p * v4.w;
            }
        }
        #pragma unroll
        for (int r = 0; r < 8; r++) {
            int t = tg*8 + r;
            xs[t*128 + o0 + 0] = acc[r][0];
            xs[t*128 + o0 + 1] = acc[r][1];
            xs[t*128 + o0 + 2] = acc[r][2];
            xs[t*128 + o0 + 3] = acc[r][3];
        }
    }
    __syncthreads();

    // A = sigmoid(ctx) * (ctx @ WgT + bg)
    for (int idx = tid; idx < 16384; idx += 256) {
        int o = idx >> 7, i = idx & 127;
        ws[i*132 + o] = Wg[idx];
    }
    __syncthreads();
    {
        float acc[8][4];
        #pragma unroll
        for (int r = 0; r < 8; r++)
            #pragma unroll
            for (int j = 0; j < 4; j++) acc[r][j] = 0.f;
        for (int i = 0; i < 128; i++) {
            float4 w4 = *(const float4*)&ws[i*132 + o0];
            #pragma unroll
            for (int r = 0; r < 8; r++) {
                float x = xs[(tg*8 + r)*128 + i];
                acc[r][0] += x * w4.x; acc[r][1] += x * w4.y;
                acc[r][2] += x * w4.z; acc[r][3] += x * w4.w;
            }
        }
        float4 bg4 = *(const float4*)&bg[o0];
        #pragma unroll
        for (int r = 0; r < 8; r++) {
            int t = tg*8 + r;
            float4 c4 = *(const float4*)&xs[t*128 + o0];
            float4 res;
            res.x = (1.f/(1.f+__expf(-c4.x))) * (acc[r][0] + bg4.x);
            res.y = (1.f/(1.f+__expf(-c4.y))) * (acc[r][1] + bg4.y);
            res.z = (1.f/(1.f+__expf(-c4.z))) * (acc[r][2] + bg4.z);
            res.w = (1.f/(1.f+__expf(-c4.w))) * (acc[r][3] + bg4.w);
            *(float4*)&g_A[(size_t)(t0 + t)*128 + o0] = res;
        }
    }
    __syncthreads();

    // B = sigmoid(ctx) * (ctx @ WbT + bb)
    for (int idx = tid; idx < 16384; idx += 256) {
        int o = idx >> 7, i = idx & 127;
        ws[i*132 + o] = Wb[idx];
    }
    __syncthreads();
    {
        float acc[8][4];
        #pragma unroll
        for (int r = 0; r < 8; r++)
            #pragma unroll
            for (int j = 0; j < 4; j++) acc[r][j] = 0.f;
        for (int i = 0; i < 128; i++) {
            float4 w4 = *(const float4*)&ws[i*132 + o0];
            #pragma unroll
            for (int r = 0; r < 8; r++) {
                float x = xs[(tg*8 + r)*128 + i];
                acc[r][0] += x * w4.x; acc[r][1] += x * w4.y;
                acc[r][2] += x * w4.z; acc[r][3] += x * w4.w;
            }
        }
        float4 bb4 = *(const float4*)&bb[o0];
        #pragma unroll
        for (int r = 0; r < 8; r++) {
            int t = tg*8 + r;
            float4 c4 = *(const float4*)&xs[t*128 + o0];
            float4 res;
            res.x = (1.f/(1.f+__expf(-c4.x))) * (acc[r][0] + bb4.x);
            res.y = (1.f/(1.f+__expf(-c4.y))) * (acc[r][1] + bb4.y);
            res.z = (1.f/(1.f+__expf(-c4.z))) * (acc[r][2] + bb4.z);
            res.w = (1.f/(1.f+__expf(-c4.w))) * (acc[r][3] + bb4.w);
            *(float4*)&g_B[(size_t)(t0 + t)*128 + o0] = res;
        }
    }
}

// ============================================================================
// Kernel 3: final — equi GEMM, tf32 mma.sync, k-chunk cp.async pipeline.
//   A = h_prime as [262144 x 128] row-major; B(k,n) = We[n][k].
// CTA: 128 rows x 128 cols, 8 warps (4x2), warp = 32 rows x 64 cols.
// smem: We tf32 [128][132] (67.6KB, resident) +
//       2 x A-chunk [128 rows][32 k + 4 pad] fp32 (36.9KB) = 104.4KB -> 2 CTA/SM.
// Pipeline: cp.async chunk kc+2 while MMA consumes chunk kc.
// A fragments cvt.rna.tf32 at use; epilogue out = h + gA*D + gB (h via L2).
// ============================================================================
#define FK_SMEM ((16896 + 2*128*36) * 4)

__device__ __forceinline__ uint32_t f2tf32(float x) {
    uint32_t u;
    asm("cvt.rna.tf32.f32 %0, %1;" : "=r"(u) : "f"(x));
    return u;
}

__device__ __forceinline__ void cp16(void* dst_smem, const void* src_gmem) {
    uint32_t d = (uint32_t)__cvta_generic_to_shared(dst_smem);
    asm volatile("cp.async.cg.shared.global [%0], [%1], 16;" :: "r"(d), "l"(src_gmem));
}

__global__ void __launch_bounds__(256, 2)
final_kernel(const float* __restrict__ h_prime,
             const float* __restrict__ We,
             const float* __restrict__ gA,
             const float* __restrict__ gB,
             float* __restrict__ out) {
    extern __shared__ uint32_t smu[];
    uint32_t* ws = smu;                              // We tf32 [128][132]
    float* ab0 = (float*)(smu + 16896);              // A chunk buf 0 [128][36]
    float* ab1 = (float*)(smu + 16896 + 128*36);     // A chunk buf 1

    int tid = threadIdx.x;
    size_t base = (size_t)blockIdx.x * 128;          // first global row

    // ---- stage We (tf32, rna) ----
    const float4* wsrc = (const float4*)We;
    #pragma unroll 4
    for (int i4 = tid; i4 < 4096; i4 += 256) {
        float4 v = wsrc[i4];
        int idx = i4 * 4;
        int r = idx >> 7, k = idx & 127;
        uint32_t* p = &ws[r*132 + k];
        p[0] = f2tf32(v.x); p[1] = f2tf32(v.y); p[2] = f2tf32(v.z); p[3] = f2tf32(v.w);
    }

    // ---- issue A chunks 0,1 (raw fp32, 128 rows x 32 k each) ----
    {
        const float* src0 = h_prime + base*128;
        #pragma unroll
        for (int i = tid; i < 1024; i += 256) {
            int r = i >> 3, q = i & 7;
            cp16(&ab0[r*36 + q*4], src0 + (size_t)r*128 + q*4);
        }
        asm volatile("cp.async.commit_group;");
        const float* src1 = h_prime + base*128 + 32;
        #pragma unroll
        for (int i = tid; i < 1024; i += 256) {
            int r = i >> 3, q = i & 7;
            cp16(&ab1[r*36 + q*4], src1 + (size_t)r*128 + q*4);
        }
        asm volatile("cp.async.commit_group;");
    }

    int w    = tid >> 5;
    int lane = tid & 31;
    int gid  = lane >> 2;
    int ctg  = lane & 3;
    int row0 = (w & 3) * 32;
    int col0 = (w >> 2) * 64;

    float acc[2][8][4];
    #pragma unroll
    for (int mi = 0; mi < 2; mi++)
        #pragma unroll
        for (int ni = 0; ni < 8; ni++)
            #pragma unroll
            for (int j = 0; j < 4; j++) acc[mi][ni][j] = 0.f;

    // ---- mainloop: 4 k-chunks of 32, double-buffered ----
    #pragma unroll
    for (int kc = 0; kc < 4; kc++) {
        if (kc < 3) asm volatile("cp.async.wait_group 1;");
        else        asm volatile("cp.async.wait_group 0;");
        __syncthreads();
        const float* buf = (kc & 1) ? ab1 : ab0;

        #pragma unroll
        for (int ks = 0; ks < 4; ks++) {
            int klo = ks * 8;
            uint32_t a[2][4];
            #pragma unroll
            for (int mi = 0; mi < 2; mi++) {
                const float* rp = buf + (row0 + mi*16 + gid)*36 + klo + ctg;
                a[mi][0] = f2tf32(rp[0]);
                a[mi][1] = f2tf32(rp[8*36]);
                a[mi][2] = f2tf32(rp[4]);
                a[mi][3] = f2tf32(rp[8*36 + 4]);
            }
            int kg = kc*32 + klo;
            #pragma unroll
            for (int ni = 0; ni < 8; ni++) {
                int nbase = (col0 + ni*8 + gid) * 132;
                uint32_t b0 = ws[nbase + kg + ctg];
                uint32_t b1 = ws[nbase + kg + ctg + 4];
                #pragma unroll
                for (int mi = 0; mi < 2; mi++) {
                    asm volatile(
                        "mma.sync.aligned.m16n8k8.row.col.f32.tf32.tf32.f32 "
                        "{%0,%1,%2,%3}, {%4,%5,%6,%7}, {%8,%9}, {%0,%1,%2,%3};"
                        : "+f"(acc[mi][ni][0]), "+f"(acc[mi][ni][1]),
                          "+f"(acc[mi][ni][2]), "+f"(acc[mi][ni][3])
                        : "r"(a[mi][0]), "r"(a[mi][1]), "r"(a[mi][2]), "r"(a[mi][3]),
                          "r"(b0), "r"(b1));
                }
            }
        }
        __syncthreads();

        if (kc + 2 < 4) {   // refill the buffer just freed with chunk kc+2
            float* dst = (kc & 1) ? ab1 : ab0;
            const float* src = h_prime + base*128 + (kc + 2)*32;
            #pragma unroll
            for (int i = tid; i < 1024; i += 256) {
                int r = i >> 3, q = i & 7;
                cp16(&dst[r*36 + q*4], src + (size_t)r*128 + q*4);
            }
            asm volatile("cp.async.commit_group;");
        }
    }

    // ---- epilogue: out = h + gA*D + gB ----
    #pragma unroll
    for (int mi = 0; mi < 2; mi++) {
        #pragma unroll
        for (int ni = 0; ni < 8; ni++) {
            int c = col0 + ni*8 + ctg*2;
            {
                size_t R = base + row0 + mi*16 + gid;
                size_t t = R >> 3;
                float2 h2 = *(const float2*)&h_prime[R*128 + c];
                float2 A2 = *(const float2*)&gA[t*128 + c];
                float2 B2 = *(const float2*)&gB[t*128 + c];
                float2 r2;
                r2.x = h2.x + A2.x * acc[mi][ni][0] + B2.x;
                r2.y = h2.y + A2.y * acc[mi][ni][1] + B2.y;
                *(float2*)&out[R*128 + c] = r2;
            }
            {
                size_t R = base + row0 + mi*16 + gid + 8;
                size_t t = R >> 3;
                float2 h2 = *(const float2*)&h_prime[R*128 + c];
                float2 A2 = *(const float2*)&gA[t*128 + c];
                float2 B2 = *(const float2*)&gB[t*128 + c];
                float2 r2;
                r2.x = h2.x + A2.x * acc[mi][ni][2] + B2.x;
                r2.y = h2.y + A2.y * acc[mi][ni][3] + B2.y;
                *(float2*)&out[R*128 + c] = r2;
            }
        }
    }
}

// ============================================================================
extern "C" void kernel_launch(void* const* d_in, const int* in_sizes, int n_in,
                              void* d_out, int out_size) {
    const float* h_prime = (const float*)d_in[0];
    const float* h_llm   = (const float*)d_in[1];
    const float* Wq = (const float*)d_in[2];
    const float* bq = (const float*)d_in[3];
    const float* Wk = (const float*)d_in[4];
    const float* bk = (const float*)d_in[5];
    const float* Wv = (const float*)d_in[6];
    const float* bv = (const float*)d_in[7];
    const float* Wg = (const float*)d_in[8];
    const float* bg = (const float*)d_in[9];
    const float* Wb = (const float*)d_in[10];
    const float* bb = (const float*)d_in[11];
    const float* We = (const float*)d_in[12];
    float* out = (float*)d_out;

    const int KV_SMEM = (8448 + 4096) * 4;
    cudaFuncSetAttribute(kv_kernel,    cudaFuncAttributeMaxDynamicSharedMemorySize, KV_SMEM);
    cudaFuncSetAttribute(mega_kernel,  cudaFuncAttributeMaxDynamicSharedMemorySize, MEGA_SMEM);
    cudaFuncSetAttribute(final_kernel, cudaFuncAttributeMaxDynamicSharedMemorySize, FK_SMEM);

    float *pA, *pB;
    cudaGetSymbolAddress((void**)&pA, g_A);
    cudaGetSymbolAddress((void**)&pB, g_B);

    kv_kernel<<<256, 256, KV_SMEM>>>(h_llm, Wk, Wv);
    kv_reduce<<<512, 256>>>(bk, bv);
    mega_kernel<<<512, 256, MEGA_SMEM>>>(h_prime, Wq, bq, Wg, bg, Wb, bb);
    final_kernel<<<2048, 256, FK_SMEM>>>(h_prime, We, pA, pB, out);
}

// round 6
// speedup vs baseline: 2.7255x; 1.4453x over previous
#include <cuda_runtime.h>
#include <math.h>
#include <stdint.h>

// Problem constants
#define B_    8
#define NE    4
#define Tn    1024
#define D_    1024
#define G_    8
#define BLK   128
#define TT    64
#define DLLM  2048
#define NT    (B_*NE*Tn)          // 32768 tokens
#define SCALEF 0.08838834764831845f  // 128^-0.5

// -------- device scratch (static, no dynamic allocation) --------
__device__ float g_kvp[16*2*8*64*128];   // K-split partials for k/v
__device__ float g_k[B_*TT*BLK];         // [8][64][128]
__device__ float g_v[B_*TT*BLK];
__device__ float g_q[NT*BLK];            // q (scaled, biased)
__device__ float g_ctx[NT*BLK];          // attention context
__device__ float g_A[NT*BLK];            // gate*gamma
__device__ float g_B[NT*BLK];            // gate*beta

__device__ __forceinline__ uint32_t f2tf32(float x) {
    uint32_t u;
    asm("cvt.rna.tf32.f32 %0, %1;" : "=r"(u) : "f"(x));
    return u;
}

__device__ __forceinline__ void cp16(void* dst_smem, const void* src_gmem) {
    uint32_t d = (uint32_t)__cvta_generic_to_shared(dst_smem);
    asm volatile("cp.async.cg.shared.global [%0], [%1], 16;" :: "r"(d), "l"(src_gmem));
}

#define MMA_TF32(acc, a0,a1,a2,a3, b0,b1) \
    asm volatile( \
        "mma.sync.aligned.m16n8k8.row.col.f32.tf32.tf32.f32 " \
        "{%0,%1,%2,%3}, {%4,%5,%6,%7}, {%8,%9}, {%0,%1,%2,%3};" \
        : "+f"(acc[0]), "+f"(acc[1]), "+f"(acc[2]), "+f"(acc[3]) \
        : "r"(a0), "r"(a1), "r"(a2), "r"(a3), "r"(b0), "r"(b1))

// ============================================================================
// Kernel 1: k/v projection, split-K GEMM (unchanged).
// ============================================================================
__global__ void kv_kernel(const float* __restrict__ h_llm,
                          const float* __restrict__ Wk,
                          const float* __restrict__ Wv) {
    extern __shared__ float sm[];
    float* ws = sm;              // [64][132]
    float* xs = sm + 64*132;     // [64][64]
    int bx = blockIdx.x;
    int slice = bx >> 4;
    int b     = (bx >> 1) & 7;
    int which = bx & 1;
    const float* W = which ? Wv : Wk;
    int kbase = slice * 128;
    int tid = threadIdx.x;
    int oq = tid & 31, sg = tid >> 5;
    int o0 = oq * 4;

    float acc[8][4];
    #pragma unroll
    for (int r = 0; r < 8; r++)
        #pragma unroll
        for (int j = 0; j < 4; j++) acc[r][j] = 0.f;

    for (int kc = 0; kc < 128; kc += 64) {
        __syncthreads();
        for (int idx = tid; idx < 64*64; idx += 256) {
            int s = idx >> 6, i = idx & 63;
            xs[s*64 + i] = h_llm[(size_t)b*TT*DLLM + (size_t)s*DLLM + kbase + kc + i];
        }
        for (int idx = tid; idx < 128*64; idx += 256) {
            int o = idx >> 6, i = idx & 63;
            ws[i*132 + o] = W[(size_t)o*DLLM + kbase + kc + i];
        }
        __syncthreads();
        for (int i = 0; i < 64; i++) {
            float4 w4 = *(const float4*)&ws[i*132 + o0];
            #pragma unroll
            for (int r = 0; r < 8; r++) {
                float x = xs[(sg*8 + r)*64 + i];
                acc[r][0] += x * w4.x; acc[r][1] += x * w4.y;
                acc[r][2] += x * w4.z; acc[r][3] += x * w4.w;
            }
        }
    }
    float* outp = g_kvp + ((size_t)(slice*2 + which)*8 + b) * (64*128);
    #pragma unroll
    for (int r = 0; r < 8; r++) {
        int s = sg*8 + r;
        float4 v4 = make_float4(acc[r][0], acc[r][1], acc[r][2], acc[r][3]);
        *(float4*)&outp[s*128 + o0] = v4;
    }
}

__global__ void kv_reduce(const float* __restrict__ bk,
                          const float* __restrict__ bv) {
    int idx = blockIdx.x * 256 + threadIdx.x;
    if (idx >= 2*8*64*128) return;
    int which = idx >> 16;
    int rem   = idx & 65535;
    int o = rem & 127;
    float s = which ? bv[o] : bk[o];
    #pragma unroll
    for (int sl = 0; sl < 16; sl++)
        s += g_kvp[(size_t)(sl*2 + which)*65536 + rem];
    (which ? g_v : g_k)[rem] = s;
}

// ============================================================================
// Kernel 2: q_kernel — fused group-maxpool + q = inv @ WqT + bq (scaled), tf32 MMA.
// CTA = 64 tokens, 8 warps (4 row-groups x 2 col-groups), warp = 16 rows x 64 cols.
// smem: Wq tf32 [128][132] + invs fp32 [64][132] = 101.4 KB -> 2 CTA/SM.
// ============================================================================
#define QK_SMEM ((16896 + 8448) * 4)

__global__ void __launch_bounds__(256)
q_kernel(const float* __restrict__ h_prime,
         const float* __restrict__ Wq, const float* __restrict__ bq) {
    extern __shared__ uint32_t smu[];
    uint32_t* ws = smu;                       // Wq tf32 [128][132]
    float* invs = (float*)(smu + 16896);      // inv [64][132]

    int tid = threadIdx.x;
    size_t t0 = (size_t)blockIdx.x * 64;

    // stage Wq (tf32, rna)
    const float4* wsrc = (const float4*)Wq;
    #pragma unroll 4
    for (int i4 = tid; i4 < 4096; i4 += 256) {
        float4 v = wsrc[i4];
        int idx = i4 * 4;
        int r = idx >> 7, k = idx & 127;
        uint32_t* p = &ws[r*132 + k];
        p[0] = f2tf32(v.x); p[1] = f2tf32(v.y); p[2] = f2tf32(v.z); p[3] = f2tf32(v.w);
    }
    // maxpool over groups: 64 tokens x 32 float4
    #pragma unroll 2
    for (int i4 = tid; i4 < 2048; i4 += 256) {
        int t = i4 >> 5, d4 = i4 & 31;
        const float4* hp = (const float4*)(h_prime + (t0 + t)*1024 + d4*4);
        float4 m = hp[0];
        #pragma unroll
        for (int g = 1; g < 8; g++) {
            float4 x = hp[g*32];
            m.x = fmaxf(m.x, x.x); m.y = fmaxf(m.y, x.y);
            m.z = fmaxf(m.z, x.z); m.w = fmaxf(m.w, x.w);
        }
        *(float4*)&invs[t*132 + d4*4] = m;
    }
    __syncthreads();

    int w = tid >> 5, lane = tid & 31;
    int gid = lane >> 2, ctg = lane & 3;
    int row0 = (w & 3) * 16;
    int col0 = (w >> 2) * 64;

    float acc[8][4];
    #pragma unroll
    for (int ni = 0; ni < 8; ni++)
        #pragma unroll
        for (int j = 0; j < 4; j++) acc[ni][j] = 0.f;

    #pragma unroll
    for (int ks = 0; ks < 16; ks++) {
        int k0 = ks * 8;
        const float* rp = invs + (row0 + gid)*132 + k0 + ctg;
        uint32_t a0 = f2tf32(rp[0]);
        uint32_t a1 = f2tf32(rp[8*132]);
        uint32_t a2 = f2tf32(rp[4]);
        uint32_t a3 = f2tf32(rp[8*132 + 4]);
        #pragma unroll
        for (int ni = 0; ni < 8; ni++) {
            int nb = (col0 + ni*8 + gid) * 132;
            uint32_t b0 = ws[nb + k0 + ctg];
            uint32_t b1 = ws[nb + k0 + ctg + 4];
            MMA_TF32(acc[ni], a0, a1, a2, a3, b0, b1);
        }
    }

    #pragma unroll
    for (int ni = 0; ni < 8; ni++) {
        int c = col0 + ni*8 + ctg*2;
        float2 b2 = *(const float2*)&bq[c];
        size_t R1 = t0 + row0 + gid;
        float2 q1;
        q1.x = (acc[ni][0] + b2.x) * SCALEF;
        q1.y = (acc[ni][1] + b2.y) * SCALEF;
        *(float2*)&g_q[R1*128 + c] = q1;
        size_t R2 = R1 + 8;
        float2 q2;
        q2.x = (acc[ni][2] + b2.x) * SCALEF;
        q2.y = (acc[ni][3] + b2.y) * SCALEF;
        *(float2*)&g_q[R2*128 + c] = q2;
    }
}

// ============================================================================
// Kernel 3: attn_kernel — scores MMA -> softmax -> ctx MMA -> g_ctx.
// CTA = 64 tokens (one batch). smem: qs [64][132] + ks [64][132] (ss aliases)
// + vsT [128][68] = 102.4 KB -> 2 CTA/SM.
// ============================================================================
#define ATTN_SMEM ((8448 + 8448 + 8704) * 4)

__global__ void __launch_bounds__(256)
attn_kernel() {
    extern __shared__ float smf[];
    float* qs = smf;             // [64][132] fp32
    float* ks = smf + 8448;      // [64][132] fp32 ; later aliased by ss [64][68]
    float* vs = smf + 16896;     // vT [128][68] fp32

    int tid = threadIdx.x;
    size_t t0 = (size_t)blockIdx.x * 64;
    int b = (int)(t0 >> 12);

    for (int i4 = tid; i4 < 2048; i4 += 256) {
        int t = i4 >> 5, d4 = i4 & 31;
        *(float4*)&qs[t*132 + d4*4] = *(const float4*)&g_q[(t0 + t)*128 + d4*4];
    }
    for (int i4 = tid; i4 < 2048; i4 += 256) {
        int s = i4 >> 5, d4 = i4 & 31;
        *(float4*)&ks[s*132 + d4*4] = *(const float4*)&g_k[(size_t)b*8192 + s*128 + d4*4];
    }
    for (int idx = tid; idx < 8192; idx += 256) {
        int s = idx >> 7, d = idx & 127;
        vs[d*68 + s] = g_v[(size_t)b*8192 + idx];
    }
    __syncthreads();

    int w = tid >> 5, lane = tid & 31;
    int gid = lane >> 2, ctg = lane & 3;
    int row0  = (w & 3) * 16;
    int col0s = (w >> 2) * 32;   // scores: N=64, 4 n-tiles per warp
    int col0c = (w >> 2) * 64;   // ctx:    N=128, 8 n-tiles per warp

    // ---- scores MMA: [64 t] x [64 s], K = 128 ----
    float sacc[4][4];
    #pragma unroll
    for (int ni = 0; ni < 4; ni++)
        #pragma unroll
        for (int j = 0; j < 4; j++) sacc[ni][j] = 0.f;

    #pragma unroll
    for (int ksx = 0; ksx < 16; ksx++) {
        int k0 = ksx * 8;
        const float* rp = qs + (row0 + gid)*132 + k0 + ctg;
        uint32_t a0 = f2tf32(rp[0]);
        uint32_t a1 = f2tf32(rp[8*132]);
        uint32_t a2 = f2tf32(rp[4]);
        uint32_t a3 = f2tf32(rp[8*132 + 4]);
        #pragma unroll
        for (int ni = 0; ni < 4; ni++) {
            const float* np = ks + (col0s + ni*8 + gid)*132 + k0 + ctg;
            uint32_t b0 = f2tf32(np[0]);
            uint32_t b1 = f2tf32(np[4]);
            MMA_TF32(sacc[ni], a0, a1, a2, a3, b0, b1);
        }
    }
    __syncthreads();   // all warps done reading ks

    float* ss = ks;    // alias, stride 68
    #pragma unroll
    for (int ni = 0; ni < 4; ni++) {
        int c = col0s + ni*8 + ctg*2;
        int r1 = row0 + gid;
        ss[r1*68 + c]     = sacc[ni][0];
        ss[r1*68 + c + 1] = sacc[ni][1];
        ss[(r1+8)*68 + c]     = sacc[ni][2];
        ss[(r1+8)*68 + c + 1] = sacc[ni][3];
    }
    __syncthreads();

    // ---- softmax over s per token row ----
    if (tid < 64) {
        float* row = ss + tid*68;
        float m = row[0];
        #pragma unroll 8
        for (int s = 1; s < 64; s++) m = fmaxf(m, row[s]);
        float sum = 0.f;
        #pragma unroll 8
        for (int s = 0; s < 64; s++) { float e = __expf(row[s] - m); row[s] = e; sum += e; }
        float inv = 1.f / sum;
        #pragma unroll 8
        for (int s = 0; s < 64; s++) row[s] *= inv;
    }
    __syncthreads();

    // ---- ctx MMA: [64 t] x [128 d], K = 64 ----
    float cacc[8][4];
    #pragma unroll
    for (int ni = 0; ni < 8; ni++)
        #pragma unroll
        for (int j = 0; j < 4; j++) cacc[ni][j] = 0.f;

    #pragma unroll
    for (int ksx = 0; ksx < 8; ksx++) {
        int k0 = ksx * 8;
        const float* rp = ss + (row0 + gid)*68 + k0 + ctg;
        uint32_t a0 = f2tf32(rp[0]);
        uint32_t a1 = f2tf32(rp[8*68]);
        uint32_t a2 = f2tf32(rp[4]);
        uint32_t a3 = f2tf32(rp[8*68 + 4]);
        #pragma unroll
        for (int ni = 0; ni < 8; ni++) {
            const float* np = vs + (col0c + ni*8 + gid)*68 + k0 + ctg;
            uint32_t b0 = f2tf32(np[0]);
            uint32_t b1 = f2tf32(np[4]);
            MMA_TF32(cacc[ni], a0, a1, a2, a3, b0, b1);
        }
    }

    #pragma unroll
    for (int ni = 0; ni < 8; ni++) {
        int c = col0c + ni*8 + ctg*2;
        size_t R1 = t0 + row0 + gid;
        *(float2*)&g_ctx[R1*128 + c] = make_float2(cacc[ni][0], cacc[ni][1]);
        size_t R2 = R1 + 8;
        *(float2*)&g_ctx[R2*128 + c] = make_float2(cacc[ni][2], cacc[ni][3]);
    }
}

// ============================================================================
// Kernel 4: gb_kernel — streaming tf32 GEMM over g_ctx with sigmoid-gated epilogue.
// blockIdx.y = 0: g_A = sigmoid(ctx)*(ctx@WgT+bg); 1: g_B with Wb/bb.
// Same cp.async k-chunk pipeline as final_kernel. 104 KB smem -> 2 CTA/SM.
// ============================================================================
#define GB_SMEM ((16896 + 2*128*36) * 4)

__global__ void __launch_bounds__(256, 2)
gb_kernel(const float* __restrict__ Wg, const float* __restrict__ bg,
          const float* __restrict__ Wb, const float* __restrict__ bb) {
    extern __shared__ uint32_t smu[];
    uint32_t* ws = smu;                              // W tf32 [128][132]
    float* ab0 = (float*)(smu + 16896);              // ctx chunk buf 0 [128][36]
    float* ab1 = (float*)(smu + 16896 + 128*36);

    const float* W    = blockIdx.y ? Wb : Wg;
    const float* bias = blockIdx.y ? bb : bg;
    float* dst        = blockIdx.y ? g_B : g_A;

    int tid = threadIdx.x;
    size_t base = (size_t)blockIdx.x * 128;          // first token row

    const float4* wsrc = (const float4*)W;
    #pragma unroll 4
    for (int i4 = tid; i4 < 4096; i4 += 256) {
        float4 v = wsrc[i4];
        int idx = i4 * 4;
        int r = idx >> 7, k = idx & 127;
        uint32_t* p = &ws[r*132 + k];
        p[0] = f2tf32(v.x); p[1] = f2tf32(v.y); p[2] = f2tf32(v.z); p[3] = f2tf32(v.w);
    }
    {
        const float* src0 = g_ctx + base*128;
        #pragma unroll
        for (int i = tid; i < 1024; i += 256) {
            int r = i >> 3, q = i & 7;
            cp16(&ab0[r*36 + q*4], src0 + (size_t)r*128 + q*4);
        }
        asm volatile("cp.async.commit_group;");
        const float* src1 = g_ctx + base*128 + 32;
        #pragma unroll
        for (int i = tid; i < 1024; i += 256) {
            int r = i >> 3, q = i & 7;
            cp16(&ab1[r*36 + q*4], src1 + (size_t)r*128 + q*4);
        }
        asm volatile("cp.async.commit_group;");
    }

    int w = tid >> 5, lane = tid & 31;
    int gid = lane >> 2, ctg = lane & 3;
    int row0 = (w & 3) * 32;
    int col0 = (w >> 2) * 64;

    float acc[2][8][4];
    #pragma unroll
    for (int mi = 0; mi < 2; mi++)
        #pragma unroll
        for (int ni = 0; ni < 8; ni++)
            #pragma unroll
            for (int j = 0; j < 4; j++) acc[mi][ni][j] = 0.f;

    #pragma unroll
    for (int kc = 0; kc < 4; kc++) {
        if (kc < 3) asm volatile("cp.async.wait_group 1;");
        else        asm volatile("cp.async.wait_group 0;");
        __syncthreads();
        const float* buf = (kc & 1) ? ab1 : ab0;

        #pragma unroll
        for (int ksx = 0; ksx < 4; ksx++) {
            int klo = ksx * 8;
            uint32_t a[2][4];
            #pragma unroll
            for (int mi = 0; mi < 2; mi++) {
                const float* rp = buf + (row0 + mi*16 + gid)*36 + klo + ctg;
                a[mi][0] = f2tf32(rp[0]);
                a[mi][1] = f2tf32(rp[8*36]);
                a[mi][2] = f2tf32(rp[4]);
                a[mi][3] = f2tf32(rp[8*36 + 4]);
            }
            int kg = kc*32 + klo;
            #pragma unroll
            for (int ni = 0; ni < 8; ni++) {
                int nb = (col0 + ni*8 + gid) * 132;
                uint32_t b0 = ws[nb + kg + ctg];
                uint32_t b1 = ws[nb + kg + ctg + 4];
                #pragma unroll
                for (int mi = 0; mi < 2; mi++)
                    MMA_TF32(acc[mi][ni], a[mi][0], a[mi][1], a[mi][2], a[mi][3], b0, b1);
            }
        }
        __syncthreads();

        if (kc + 2 < 4) {
            float* dstb = (kc & 1) ? ab1 : ab0;
            const float* src = g_ctx + base*128 + (kc + 2)*32;
            #pragma unroll
            for (int i = tid; i < 1024; i += 256) {
                int r = i >> 3, q = i & 7;
                cp16(&dstb[r*36 + q*4], src + (size_t)r*128 + q*4);
            }
            asm volatile("cp.async.commit_group;");
        }
    }

    // epilogue: dst = sigmoid(ctx) * (acc + bias)
    #pragma unroll
    for (int mi = 0; mi < 2; mi++) {
        #pragma unroll
        for (int ni = 0; ni < 8; ni++) {
            int c = col0 + ni*8 + ctg*2;
            float2 b2 = *(const float2*)&bias[c];
            {
                size_t R = base + row0 + mi*16 + gid;
                float2 c2 = *(const float2*)&g_ctx[R*128 + c];
                float2 r2;
                r2.x = (1.f/(1.f+__expf(-c2.x))) * (acc[mi][ni][0] + b2.x);
                r2.y = (1.f/(1.f+__expf(-c2.y))) * (acc[mi][ni][1] + b2.y);
                *(float2*)&dst[R*128 + c] = r2;
            }
            {
                size_t R = base + row0 + mi*16 + gid + 8;
                float2 c2 = *(const float2*)&g_ctx[R*128 + c];
                float2 r2;
                r2.x = (1.f/(1.f+__expf(-c2.x))) * (acc[mi][ni][2] + b2.x);
                r2.y = (1.f/(1.f+__expf(-c2.y))) * (acc[mi][ni][3] + b2.y);
                *(float2*)&dst[R*128 + c] = r2;
            }
        }
    }
}

// ============================================================================
// Kernel 5: final — equi GEMM, tf32 MMA, cp.async k-chunk pipeline (unchanged).
// ============================================================================
#define FK_SMEM ((16896 + 2*128*36) * 4)

__global__ void __launch_bounds__(256, 2)
final_kernel(const float* __restrict__ h_prime,
             const float* __restrict__ We,
             float* __restrict__ out) {
    extern __shared__ uint32_t smu[];
    uint32_t* ws = smu;
    float* ab0 = (float*)(smu + 16896);
    float* ab1 = (float*)(smu + 16896 + 128*36);

    int tid = threadIdx.x;
    size_t base = (size_t)blockIdx.x * 128;

    const float4* wsrc = (const float4*)We;
    #pragma unroll 4
    for (int i4 = tid; i4 < 4096; i4 += 256) {
        float4 v = wsrc[i4];
        int idx = i4 * 4;
        int r = idx >> 7, k = idx & 127;
        uint32_t* p = &ws[r*132 + k];
        p[0] = f2tf32(v.x); p[1] = f2tf32(v.y); p[2] = f2tf32(v.z); p[3] = f2tf32(v.w);
    }
    {
        const float* src0 = h_prime + base*128;
        #pragma unroll
        for (int i = tid; i < 1024; i += 256) {
            int r = i >> 3, q = i & 7;
            cp16(&ab0[r*36 + q*4], src0 + (size_t)r*128 + q*4);
        }
        asm volatile("cp.async.commit_group;");
        const float* src1 = h_prime + base*128 + 32;
        #pragma unroll
        for (int i = tid; i < 1024; i += 256) {
            int r = i >> 3, q = i & 7;
            cp16(&ab1[r*36 + q*4], src1 + (size_t)r*128 + q*4);
        }
        asm volatile("cp.async.commit_group;");
    }

    int w = tid >> 5, lane = tid & 31;
    int gid = lane >> 2, ctg = lane & 3;
    int row0 = (w & 3) * 32;
    int col0 = (w >> 2) * 64;

    float acc[2][8][4];
    #pragma unroll
    for (int mi = 0; mi < 2; mi++)
        #pragma unroll
        for (int ni = 0; ni < 8; ni++)
            #pragma unroll
            for (int j = 0; j < 4; j++) acc[mi][ni][j] = 0.f;

    #pragma unroll
    for (int kc = 0; kc < 4; kc++) {
        if (kc < 3) asm volatile("cp.async.wait_group 1;");
        else        asm volatile("cp.async.wait_group 0;");
        __syncthreads();
        const float* buf = (kc & 1) ? ab1 : ab0;

        #pragma unroll
        for (int ksx = 0; ksx < 4; ksx++) {
            int klo = ksx * 8;
            uint32_t a[2][4];
            #pragma unroll
            for (int mi = 0; mi < 2; mi++) {
                const float* rp = buf + (row0 + mi*16 + gid)*36 + klo + ctg;
                a[mi][0] = f2tf32(rp[0]);
                a[mi][1] = f2tf32(rp[8*36]);
                a[mi][2] = f2tf32(rp[4]);
                a[mi][3] = f2tf32(rp[8*36 + 4]);
            }
            int kg = kc*32 + klo;
            #pragma unroll
            for (int ni = 0; ni < 8; ni++) {
                int nb = (col0 + ni*8 + gid) * 132;
                uint32_t b0 = ws[nb + kg + ctg];
                uint32_t b1 = ws[nb + kg + ctg + 4];
                #pragma unroll
                for (int mi = 0; mi < 2; mi++)
                    MMA_TF32(acc[mi][ni], a[mi][0], a[mi][1], a[mi][2], a[mi][3], b0, b1);
            }
        }
        __syncthreads();

        if (kc + 2 < 4) {
            float* dstb = (kc & 1) ? ab1 : ab0;
            const float* src = h_prime + base*128 + (kc + 2)*32;
            #pragma unroll
            for (int i = tid; i < 1024; i += 256) {
                int r = i >> 3, q = i & 7;
                cp16(&dstb[r*36 + q*4], src + (size_t)r*128 + q*4);
            }
            asm volatile("cp.async.commit_group;");
        }
    }

    #pragma unroll
    for (int mi = 0; mi < 2; mi++) {
        #pragma unroll
        for (int ni = 0; ni < 8; ni++) {
            int c = col0 + ni*8 + ctg*2;
            {
                size_t R = base + row0 + mi*16 + gid;
                size_t t = R >> 3;
                float2 h2 = *(const float2*)&h_prime[R*128 + c];
                float2 A2 = *(const float2*)&g_A[t*128 + c];
                float2 B2 = *(const float2*)&g_B[t*128 + c];
                float2 r2;
                r2.x = h2.x + A2.x * acc[mi][ni][0] + B2.x;
                r2.y = h2.y + A2.y * acc[mi][ni][1] + B2.y;
                *(float2*)&out[R*128 + c] = r2;
            }
            {
                size_t R = base + row0 + mi*16 + gid + 8;
                size_t t = R >> 3;
                float2 h2 = *(const float2*)&h_prime[R*128 + c];
                float2 A2 = *(const float2*)&g_A[t*128 + c];
                float2 B2 = *(const float2*)&g_B[t*128 + c];
                float2 r2;
                r2.x = h2.x + A2.x * acc[mi][ni][2] + B2.x;
                r2.y = h2.y + A2.y * acc[mi][ni][3] + B2.y;
                *(float2*)&out[R*128 + c] = r2;
            }
        }
    }
}

// ============================================================================
extern "C" void kernel_launch(void* const* d_in, const int* in_sizes, int n_in,
                              void* d_out, int out_size) {
    const float* h_prime = (const float*)d_in[0];
    const float* h_llm   = (const float*)d_in[1];
    const float* Wq = (const float*)d_in[2];
    const float* bq = (const float*)d_in[3];
    const float* Wk = (const float*)d_in[4];
    const float* bk = (const float*)d_in[5];
    const float* Wv = (const float*)d_in[6];
    const float* bv = (const float*)d_in[7];
    const float* Wg = (const float*)d_in[8];
    const float* bg = (const float*)d_in[9];
    const float* Wb = (const float*)d_in[10];
    const float* bb = (const float*)d_in[11];
    const float* We = (const float*)d_in[12];
    float* out = (float*)d_out;

    const int KV_SMEM = (8448 + 4096) * 4;
    cudaFuncSetAttribute(kv_kernel,    cudaFuncAttributeMaxDynamicSharedMemorySize, KV_SMEM);
    cudaFuncSetAttribute(q_kernel,     cudaFuncAttributeMaxDynamicSharedMemorySize, QK_SMEM);
    cudaFuncSetAttribute(attn_kernel,  cudaFuncAttributeMaxDynamicSharedMemorySize, ATTN_SMEM);
    cudaFuncSetAttribute(gb_kernel,    cudaFuncAttributeMaxDynamicSharedMemorySize, GB_SMEM);
    cudaFuncSetAttribute(final_kernel, cudaFuncAttributeMaxDynamicSharedMemorySize, FK_SMEM);

    kv_kernel<<<256, 256, KV_SMEM>>>(h_llm, Wk, Wv);
    kv_reduce<<<512, 256>>>(bk, bv);
    q_kernel<<<512, 256, QK_SMEM>>>(h_prime, Wq, bq);
    attn_kernel<<<512, 256, ATTN_SMEM>>>();
    gb_kernel<<<dim3(256, 2), 256, GB_SMEM>>>(Wg, bg, Wb, bb);
    final_kernel<<<2048, 256, FK_SMEM>>>(h_prime, We, out);
}

// round 8
// speedup vs baseline: 2.8337x; 1.0397x over previous
#include <cuda_runtime.h>
#include <math.h>
#include <stdint.h>

// Problem constants
#define B_    8
#define NE    4
#define Tn    1024
#define D_    1024
#define G_    8
#define BLK   128
#define TT    64
#define DLLM  2048
#define NT    (B_*NE*Tn)          // 32768 tokens
#define SCALEF 0.08838834764831845f  // 128^-0.5

// -------- device scratch (static, no dynamic allocation) --------
__device__ float g_kvp[16*2*8*64*128];   // K-split partials for k/v
__device__ float g_k[B_*TT*BLK];         // [8][64][128]
__device__ float g_v[B_*TT*BLK];
__device__ float g_A[NT*BLK];            // gate*gamma
__device__ float g_B[NT*BLK];            // gate*beta

__device__ __forceinline__ uint32_t f2tf32(float x) {
    uint32_t u;
    asm("cvt.rna.tf32.f32 %0, %1;" : "=r"(u) : "f"(x));
    return u;
}

__device__ __forceinline__ void cp16(void* dst_smem, const void* src_gmem) {
    uint32_t d = (uint32_t)__cvta_generic_to_shared(dst_smem);
    asm volatile("cp.async.cg.shared.global [%0], [%1], 16;" :: "r"(d), "l"(src_gmem));
}

#define MMA_TF32(acc, a0,a1,a2,a3, b0,b1) \
    asm volatile( \
        "mma.sync.aligned.m16n8k8.row.col.f32.tf32.tf32.f32 " \
        "{%0,%1,%2,%3}, {%4,%5,%6,%7}, {%8,%9}, {%0,%1,%2,%3};" \
        : "+f"(acc[0]), "+f"(acc[1]), "+f"(acc[2]), "+f"(acc[3]) \
        : "r"(a0), "r"(a1), "r"(a2), "r"(a3), "r"(b0), "r"(b1))

// ============================================================================
// Kernel 1: k/v projection, split-K GEMM (unchanged).
// ============================================================================
__global__ void kv_kernel(const float* __restrict__ h_llm,
                          const float* __restrict__ Wk,
                          const float* __restrict__ Wv) {
    extern __shared__ float sm[];
    float* ws = sm;              // [64][132]
    float* xs = sm + 64*132;     // [64][64]
    int bx = blockIdx.x;
    int slice = bx >> 4;
    int b     = (bx >> 1) & 7;
    int which = bx & 1;
    const float* W = which ? Wv : Wk;
    int kbase = slice * 128;
    int tid = threadIdx.x;
    int oq = tid & 31, sg = tid >> 5;
    int o0 = oq * 4;

    float acc[8][4];
    #pragma unroll
    for (int r = 0; r < 8; r++)
        #pragma unroll
        for (int j = 0; j < 4; j++) acc[r][j] = 0.f;

    for (int kc = 0; kc < 128; kc += 64) {
        __syncthreads();
        for (int idx = tid; idx < 64*64; idx += 256) {
            int s = idx >> 6, i = idx & 63;
            xs[s*64 + i] = h_llm[(size_t)b*TT*DLLM + (size_t)s*DLLM + kbase + kc + i];
        }
        for (int idx = tid; idx < 128*64; idx += 256) {
            int o = idx >> 6, i = idx & 63;
            ws[i*132 + o] = W[(size_t)o*DLLM + kbase + kc + i];
        }
        __syncthreads();
        for (int i = 0; i < 64; i++) {
            float4 w4 = *(const float4*)&ws[i*132 + o0];
            #pragma unroll
            for (int r = 0; r < 8; r++) {
                float x = xs[(sg*8 + r)*64 + i];
                acc[r][0] += x * w4.x; acc[r][1] += x * w4.y;
                acc[r][2] += x * w4.z; acc[r][3] += x * w4.w;
            }
        }
    }
    float* outp = g_kvp + ((size_t)(slice*2 + which)*8 + b) * (64*128);
    #pragma unroll
    for (int r = 0; r < 8; r++) {
        int s = sg*8 + r;
        float4 v4 = make_float4(acc[r][0], acc[r][1], acc[r][2], acc[r][3]);
        *(float4*)&outp[s*128 + o0] = v4;
    }
}

__global__ void kv_reduce(const float* __restrict__ bk,
                          const float* __restrict__ bv) {
    int idx = blockIdx.x * 256 + threadIdx.x;
    if (idx >= 2*8*64*128) return;
    int which = idx >> 16;
    int rem   = idx & 65535;
    int o = rem & 127;
    float s = which ? bv[o] : bk[o];
    #pragma unroll
    for (int sl = 0; sl < 16; sl++)
        s += g_kvp[(size_t)(sl*2 + which)*65536 + rem];
    (which ? g_v : g_k)[rem] = s;
}

// ============================================================================
// Kernel 2: mega2 — fully fused maxpool -> q -> attention -> gamma/beta.
// CTA = 64 tokens. All intermediates (inv, q, scores, ctx) stay in smem.
// smem arena (floats): R1 = 17152 (weights / k+vT / ss), R2 = 8448 (inv/q/ctx)
//  => 102.4 KB -> 2 CTA/SM.
// Phases: Wq+maxpool | qMMA | q->smem + load k,vT | scores | softmax | ctx |
//         ctx->smem + Wg | gammaMMA | g_A + Wb | betaMMA | g_B
// ============================================================================
#define M2_SMEM (25600 * 4)

__global__ void __launch_bounds__(256)
mega2_kernel(const float* __restrict__ h_prime,
             const float* __restrict__ Wq, const float* __restrict__ bq,
             const float* __restrict__ Wg, const float* __restrict__ bg,
             const float* __restrict__ Wb, const float* __restrict__ bb) {
    extern __shared__ float smf[];
    float* R1 = smf;                 // 17152 floats
    float* R2 = smf + 17152;         // 8448 floats: inv -> q -> ctx, stride 132
    uint32_t* ws = (uint32_t*)R1;    // weight view (tf32), [128][132]
    float* kbuf = R1;                // k [64][132]
    float* vbuf = R1 + 8448;         // vT [128][68]
    float* ss   = R1;                // scores [64][68] (aliases kbuf after scores)

    int tid = threadIdx.x;
    size_t t0 = (size_t)blockIdx.x * 64;
    int b = (int)(t0 >> 12);

    int w = tid >> 5, lane = tid & 31;
    int gid = lane >> 2, ctg = lane & 3;
    int row0  = (w & 3) * 16;        // 16-row group per warp
    int col0  = (w >> 2) * 64;       // N=128 phases
    int col0s = (w >> 2) * 32;       // N=64 phase (scores)

    // ---- P0: stage Wq (tf32) + maxpool inv -> R2 ----
    {
        const float4* wsrc = (const float4*)Wq;
        #pragma unroll 4
        for (int i4 = tid; i4 < 4096; i4 += 256) {
            float4 v = wsrc[i4];
            int idx = i4 * 4;
            int r = idx >> 7, k = idx & 127;
            uint32_t* p = &ws[r*132 + k];
            p[0] = f2tf32(v.x); p[1] = f2tf32(v.y); p[2] = f2tf32(v.z); p[3] = f2tf32(v.w);
        }
        #pragma unroll 2
        for (int i4 = tid; i4 < 2048; i4 += 256) {
            int t = i4 >> 5, d4 = i4 & 31;
            const float4* hp = (const float4*)(h_prime + (t0 + t)*1024 + d4*4);
            float4 m = hp[0];
            #pragma unroll
            for (int g = 1; g < 8; g++) {
                float4 x = hp[g*32];
                m.x = fmaxf(m.x, x.x); m.y = fmaxf(m.y, x.y);
                m.z = fmaxf(m.z, x.z); m.w = fmaxf(m.w, x.w);
            }
            *(float4*)&R2[t*132 + d4*4] = m;
        }
    }
    __syncthreads();

    // ---- P1: q = inv @ WqT (MMA) ----
    float qacc[8][4];
    #pragma unroll
    for (int ni = 0; ni < 8; ni++)
        #pragma unroll
        for (int j = 0; j < 4; j++) qacc[ni][j] = 0.f;
    #pragma unroll
    for (int ks = 0; ks < 16; ks++) {
        int k0 = ks * 8;
        const float* rp = R2 + (row0 + gid)*132 + k0 + ctg;
        uint32_t a0 = f2tf32(rp[0]);
        uint32_t a1 = f2tf32(rp[8*132]);
        uint32_t a2 = f2tf32(rp[4]);
        uint32_t a3 = f2tf32(rp[8*132 + 4]);
        #pragma unroll
        for (int ni = 0; ni < 8; ni++) {
            int nb = (col0 + ni*8 + gid) * 132;
            uint32_t b0 = ws[nb + k0 + ctg];
            uint32_t b1 = ws[nb + k0 + ctg + 4];
            MMA_TF32(qacc[ni], a0, a1, a2, a3, b0, b1);
        }
    }
    __syncthreads();   // done reading Wq + inv

    // ---- P2: write q (scaled+biased) over inv; load k + vT ----
    #pragma unroll
    for (int ni = 0; ni < 8; ni++) {
        int c = col0 + ni*8 + ctg*2;
        float2 b2 = *(const float2*)&bq[c];
        int r1 = row0 + gid;
        R2[r1*132 + c]     = (qacc[ni][0] + b2.x) * SCALEF;
        R2[r1*132 + c + 1] = (qacc[ni][1] + b2.y) * SCALEF;
        R2[(r1+8)*132 + c]     = (qacc[ni][2] + b2.x) * SCALEF;
        R2[(r1+8)*132 + c + 1] = (qacc[ni][3] + b2.y) * SCALEF;
    }
    for (int i4 = tid; i4 < 2048; i4 += 256) {
        int s = i4 >> 5, d4 = i4 & 31;
        *(float4*)&kbuf[s*132 + d4*4] = *(const float4*)&g_k[(size_t)b*8192 + s*128 + d4*4];
    }
    for (int idx = tid; idx < 8192; idx += 256) {
        int s = idx >> 7, d = idx & 127;
        vbuf[d*68 + s] = g_v[(size_t)b*8192 + idx];
    }
    __syncthreads();

    // ---- P3: scores = q @ kT (MMA, N=64, K=128) ----
    float sacc[4][4];
    #pragma unroll
    for (int ni = 0; ni < 4; ni++)
        #pragma unroll
        for (int j = 0; j < 4; j++) sacc[ni][j] = 0.f;
    #pragma unroll
    for (int ks = 0; ks < 16; ks++) {
        int k0 = ks * 8;
        const float* rp = R2 + (row0 + gid)*132 + k0 + ctg;
        uint32_t a0 = f2tf32(rp[0]);
        uint32_t a1 = f2tf32(rp[8*132]);
        uint32_t a2 = f2tf32(rp[4]);
        uint32_t a3 = f2tf32(rp[8*132 + 4]);
        #pragma unroll
        for (int ni = 0; ni < 4; ni++) {
            const float* np = kbuf + (col0s + ni*8 + gid)*132 + k0 + ctg;
            uint32_t b0 = f2tf32(np[0]);
            uint32_t b1 = f2tf32(np[4]);
            MMA_TF32(sacc[ni], a0, a1, a2, a3, b0, b1);
        }
    }
    __syncthreads();   // k dead

    // ---- P4: write scores (stride 68, aliases kbuf) ----
    #pragma unroll
    for (int ni = 0; ni < 4; ni++) {
        int c = col0s + ni*8 + ctg*2;
        int r1 = row0 + gid;
        ss[r1*68 + c]     = sacc[ni][0];
        ss[r1*68 + c + 1] = sacc[ni][1];
        ss[(r1+8)*68 + c]     = sacc[ni][2];
        ss[(r1+8)*68 + c + 1] = sacc[ni][3];
    }
    __syncthreads();

    // ---- P5: softmax per token row ----
    if (tid < 64) {
        float* row = ss + tid*68;
        float m = row[0];
        #pragma unroll 8
        for (int s = 1; s < 64; s++) m = fmaxf(m, row[s]);
        float sum = 0.f;
        #pragma unroll 8
        for (int s = 0; s < 64; s++) { float e = __expf(row[s] - m); row[s] = e; sum += e; }
        float inv = 1.f / sum;
        #pragma unroll 8
        for (int s = 0; s < 64; s++) row[s] *= inv;
    }
    __syncthreads();

    // ---- P6: ctx = attn @ v (MMA, N=128, K=64) ----
    float cacc[8][4];
    #pragma unroll
    for (int ni = 0; ni < 8; ni++)
        #pragma unroll
        for (int j = 0; j < 4; j++) cacc[ni][j] = 0.f;
    #pragma unroll
    for (int ks = 0; ks < 8; ks++) {
        int k0 = ks * 8;
        const float* rp = ss + (row0 + gid)*68 + k0 + ctg;
        uint32_t a0 = f2tf32(rp[0]);
        uint32_t a1 = f2tf32(rp[8*68]);
        uint32_t a2 = f2tf32(rp[4]);
        uint32_t a3 = f2tf32(rp[8*68 + 4]);
        #pragma unroll
        for (int ni = 0; ni < 8; ni++) {
            const float* np = vbuf + (col0 + ni*8 + gid)*68 + k0 + ctg;
            uint32_t b0 = f2tf32(np[0]);
            uint32_t b1 = f2tf32(np[4]);
            MMA_TF32(cacc[ni], a0, a1, a2, a3, b0, b1);
        }
    }
    __syncthreads();   // ss + vT dead, q (R2) dead

    // ---- P7: write ctx over q; stage Wg ----
    #pragma unroll
    for (int ni = 0; ni < 8; ni++) {
        int c = col0 + ni*8 + ctg*2;
        int r1 = row0 + gid;
        R2[r1*132 + c]     = cacc[ni][0];
        R2[r1*132 + c + 1] = cacc[ni][1];
        R2[(r1+8)*132 + c]     = cacc[ni][2];
        R2[(r1+8)*132 + c + 1] = cacc[ni][3];
    }
    {
        const float4* wsrc = (const float4*)Wg;
        #pragma unroll 4
        for (int i4 = tid; i4 < 4096; i4 += 256) {
            float4 v = wsrc[i4];
            int idx = i4 * 4;
            int r = idx >> 7, k = idx & 127;
            uint32_t* p = &ws[r*132 + k];
            p[0] = f2tf32(v.x); p[1] = f2tf32(v.y); p[2] = f2tf32(v.z); p[3] = f2tf32(v.w);
        }
    }
    __syncthreads();

    // ---- P8: gamma MMA ----
    float gacc[8][4];
    #pragma unroll
    for (int ni = 0; ni < 8; ni++)
        #pragma unroll
        for (int j = 0; j < 4; j++) gacc[ni][j] = 0.f;
    #pragma unroll
    for (int ks = 0; ks < 16; ks++) {
        int k0 = ks * 8;
        const float* rp = R2 + (row0 + gid)*132 + k0 + ctg;
        uint32_t a0 = f2tf32(rp[0]);
        uint32_t a1 = f2tf32(rp[8*132]);
        uint32_t a2 = f2tf32(rp[4]);
        uint32_t a3 = f2tf32(rp[8*132 + 4]);
        #pragma unroll
        for (int ni = 0; ni < 8; ni++) {
            int nb = (col0 + ni*8 + gid) * 132;
            uint32_t b0 = ws[nb + k0 + ctg];
            uint32_t b1 = ws[nb + k0 + ctg + 4];
            MMA_TF32(gacc[ni], a0, a1, a2, a3, b0, b1);
        }
    }
    __syncthreads();   // Wg dead

    // ---- P9: g_A = sigmoid(ctx)*(gacc+bg); stage Wb ----
    #pragma unroll
    for (int ni = 0; ni < 8; ni++) {
        int c = col0 + ni*8 + ctg*2;
        float2 b2 = *(const float2*)&bg[c];
        int r1 = row0 + gid;
        {
            float cx = R2[r1*132 + c], cy = R2[r1*132 + c + 1];
            float2 r2;
            r2.x = (1.f/(1.f+__expf(-cx))) * (gacc[ni][0] + b2.x);
            r2.y = (1.f/(1.f+__expf(-cy))) * (gacc[ni][1] + b2.y);
            *(float2*)&g_A[(t0 + r1)*128 + c] = r2;
        }
        {
            float cx = R2[(r1+8)*132 + c], cy = R2[(r1+8)*132 + c + 1];
            float2 r2;
            r2.x = (1.f/(1.f+__expf(-cx))) * (gacc[ni][2] + b2.x);
            r2.y = (1.f/(1.f+__expf(-cy))) * (gacc[ni][3] + b2.y);
            *(float2*)&g_A[(t0 + r1 + 8)*128 + c] = r2;
        }
    }
    {
        const float4* wsrc = (const float4*)Wb;
        #pragma unroll 4
        for (int i4 = tid; i4 < 4096; i4 += 256) {
            float4 v = wsrc[i4];
            int idx = i4 * 4;
            int r = idx >> 7, k = idx & 127;
            uint32_t* p = &ws[r*132 + k];
            p[0] = f2tf32(v.x); p[1] = f2tf32(v.y); p[2] = f2tf32(v.z); p[3] = f2tf32(v.w);
        }
    }
    __syncthreads();

    // ---- P10: beta MMA ----
    float bacc[8][4];
    #pragma unroll
    for (int ni = 0; ni < 8; ni++)
        #pragma unroll
        for (int j = 0; j < 4; j++) bacc[ni][j] = 0.f;
    #pragma unroll
    for (int ks = 0; ks < 16; ks++) {
        int k0 = ks * 8;
        const float* rp = R2 + (row0 + gid)*132 + k0 + ctg;
        uint32_t a0 = f2tf32(rp[0]);
        uint32_t a1 = f2tf32(rp[8*132]);
        uint32_t a2 = f2tf32(rp[4]);
        uint32_t a3 = f2tf32(rp[8*132 + 4]);
        #pragma unroll
        for (int ni = 0; ni < 8; ni++) {
            int nb = (col0 + ni*8 + gid) * 132;
            uint32_t b0 = ws[nb + k0 + ctg];
            uint32_t b1 = ws[nb + k0 + ctg + 4];
            MMA_TF32(bacc[ni], a0, a1, a2, a3, b0, b1);
        }
    }

    // ---- P11: g_B = sigmoid(ctx)*(bacc+bb) ----
    #pragma unroll
    for (int ni = 0; ni < 8; ni++) {
        int c = col0 + ni*8 + ctg*2;
        float2 b2 = *(const float2*)&bb[c];
        int r1 = row0 + gid;
        {
            float cx = R2[r1*132 + c], cy = R2[r1*132 + c + 1];
            float2 r2;
            r2.x = (1.f/(1.f+__expf(-cx))) * (bacc[ni][0] + b2.x);
            r2.y = (1.f/(1.f+__expf(-cy))) * (bacc[ni][1] + b2.y);
            *(float2*)&g_B[(t0 + r1)*128 + c] = r2;
        }
        {
            float cx = R2[(r1+8)*132 + c], cy = R2[(r1+8)*132 + c + 1];
            float2 r2;
            r2.x = (1.f/(1.f+__expf(-cx))) * (bacc[ni][2] + b2.x);
            r2.y = (1.f/(1.f+__expf(-cy))) * (bacc[ni][3] + b2.y);
            *(float2*)&g_B[(t0 + r1 + 8)*128 + c] = r2;
        }
    }
}

// ============================================================================
// Kernel 3: final — PERSISTENT equi GEMM. grid = 296 CTAs (2/SM).
// We staged ONCE per CTA; cp.async k-chunk pipeline chained across tiles so
// tile i's epilogue overlaps tile i+1's loads.
// ============================================================================
#define FK_GRID 296
#define FK_SMEM ((16896 + 2*128*36) * 4)

__global__ void __launch_bounds__(256, 2)
final_kernel(const float* __restrict__ h_prime,
             const float* __restrict__ We,
             float* __restrict__ out) {
    extern __shared__ uint32_t smu[];
    uint32_t* ws = smu;                          // We tf32 [128][132]
    float* bufs[2];
    bufs[0] = (float*)(smu + 16896);             // A chunk [128][36]
    bufs[1] = (float*)(smu + 16896 + 128*36);

    int tid = threadIdx.x;
    int bid = blockIdx.x;

    // stage We once
    const float4* wsrc = (const float4*)We;
    #pragma unroll 4
    for (int i4 = tid; i4 < 4096; i4 += 256) {
        float4 v = wsrc[i4];
        int idx = i4 * 4;
        int r = idx >> 7, k = idx & 127;
        uint32_t* p = &ws[r*132 + k];
        p[0] = f2tf32(v.x); p[1] = f2tf32(v.y); p[2] = f2tf32(v.z); p[3] = f2tf32(v.w);
    }

    int ntiles = (2048 - bid + FK_GRID - 1) / FK_GRID;
    int nch = ntiles * 4;

    // issue chunks 0,1
    #pragma unroll
    for (int n = 0; n < 2; n++) {
        size_t tile = bid;  // n>>2 == 0
        const float* src = h_prime + tile*16384 + n*32;
        float* dst = bufs[n];
        #pragma unroll
        for (int i = tid; i < 1024; i += 256) {
            int r = i >> 3, q = i & 7;
            cp16(&dst[r*36 + q*4], src + (size_t)r*128 + q*4);
        }
        asm volatile("cp.async.commit_group;");
    }

    int w = tid >> 5, lane = tid & 31;
    int gid = lane >> 2, ctg = lane & 3;
    int row0 = (w & 3) * 32;
    int col0 = (w >> 2) * 64;

    float acc[2][8][4];
    #pragma unroll
    for (int mi = 0; mi < 2; mi++)
        #pragma unroll
        for (int ni = 0; ni < 8; ni++)
            #pragma unroll
            for (int j = 0; j < 4; j++) acc[mi][ni][j] = 0.f;

    for (int n = 0; n < nch; n++) {
        if (n == nch - 1) asm volatile("cp.async.wait_group 0;");
        else              asm volatile("cp.async.wait_group 1;");
        __syncthreads();
        const float* buf = bufs[n & 1];
        int kc = n & 3;
        size_t tile = (size_t)bid + (size_t)(n >> 2) * FK_GRID;

        #pragma unroll
        for (int ksx = 0; ksx < 4; ksx++) {
            int klo = ksx * 8;
            uint32_t a[2][4];
            #pragma unroll
            for (int mi = 0; mi < 2; mi++) {
                const float* rp = buf + (row0 + mi*16 + gid)*36 + klo + ctg;
                a[mi][0] = f2tf32(rp[0]);
                a[mi][1] = f2tf32(rp[8*36]);
                a[mi][2] = f2tf32(rp[4]);
                a[mi][3] = f2tf32(rp[8*36 + 4]);
            }
            int kg = kc*32 + klo;
            #pragma unroll
            for (int ni = 0; ni < 8; ni++) {
                int nb = (col0 + ni*8 + gid) * 132;
                uint32_t b0 = ws[nb + kg + ctg];
                uint32_t b1 = ws[nb + kg + ctg + 4];
                #pragma unroll
                for (int mi = 0; mi < 2; mi++)
                    MMA_TF32(acc[mi][ni], a[mi][0], a[mi][1], a[mi][2], a[mi][3], b0, b1);
            }
        }
        __syncthreads();

        // refill this buffer with chunk n+2
        if (n + 2 < nch) {
            int n2 = n + 2;
            size_t tile2 = (size_t)bid + (size_t)(n2 >> 2) * FK_GRID;
            const float* src = h_prime + tile2*16384 + (n2 & 3)*32;
            float* dst = bufs[n & 1];
            #pragma unroll
            for (int i = tid; i < 1024; i += 256) {
                int r = i >> 3, q = i & 7;
                cp16(&dst[r*36 + q*4], src + (size_t)r*128 + q*4);
            }
            asm volatile("cp.async.commit_group;");
        }

        // epilogue at end of each tile (overlaps next tile's in-flight loads)
        if (kc == 3) {
            size_t base = tile * 128;
            #pragma unroll
            for (int mi = 0; mi < 2; mi++) {
                #pragma unroll
                for (int ni = 0; ni < 8; ni++) {
                    int c = col0 + ni*8 + ctg*2;
                    {
                        size_t R = base + row0 + mi*16 + gid;
                        size_t t = R >> 3;
                        float2 h2 = *(const float2*)&h_prime[R*128 + c];
                        float2 A2 = *(const float2*)&g_A[t*128 + c];
                        float2 B2 = *(const float2*)&g_B[t*128 + c];
                        float2 r2;
                        r2.x = h2.x + A2.x * acc[mi][ni][0] + B2.x;
                        r2.y = h2.y + A2.y * acc[mi][ni][1] + B2.y;
                        *(float2*)&out[R*128 + c] = r2;
                    }
                    {
                        size_t R = base + row0 + mi*16 + gid + 8;
                        size_t t = R >> 3;
                        float2 h2 = *(const float2*)&h_prime[R*128 + c];
                        float2 A2 = *(const float2*)&g_A[t*128 + c];
                        float2 B2 = *(const float2*)&g_B[t*128 + c];
                        float2 r2;
                        r2.x = h2.x + A2.x * acc[mi][ni][2] + B2.x;
                        r2.y = h2.y + A2.y * acc[mi][ni][3] + B2.y;
                        *(float2*)&out[R*128 + c] = r2;
                    }
                    #pragma unroll
                    for (int j = 0; j < 4; j++) acc[mi][ni][j] = 0.f;
                }
            }
        }
    }
}

// ============================================================================
extern "C" void kernel_launch(void* const* d_in, const int* in_sizes, int n_in,
                              void* d_out, int out_size) {
    const float* h_prime = (const float*)d_in[0];
    const float* h_llm   = (const float*)d_in[1];
    const float* Wq = (const float*)d_in[2];
    const float* bq = (const float*)d_in[3];
    const float* Wk = (const float*)d_in[4];
    const float* bk = (const float*)d_in[5];
    const float* Wv = (const float*)d_in[6];
    const float* bv = (const float*)d_in[7];
    const float* Wg = (const float*)d_in[8];
    const float* bg = (const float*)d_in[9];
    const float* Wb = (const float*)d_in[10];
    const float* bb = (const float*)d_in[11];
    const float* We = (const float*)d_in[12];
    float* out = (float*)d_out;

    const int KV_SMEM = (8448 + 4096) * 4;
    cudaFuncSetAttribute(kv_kernel,    cudaFuncAttributeMaxDynamicSharedMemorySize, KV_SMEM);
    cudaFuncSetAttribute(mega2_kernel, cudaFuncAttributeMaxDynamicSharedMemorySize, M2_SMEM);
    cudaFuncSetAttribute(final_kernel, cudaFuncAttributeMaxDynamicSharedMemorySize, FK_SMEM);

    kv_kernel<<<256, 256, KV_SMEM>>>(h_llm, Wk, Wv);
    kv_reduce<<<512, 256>>>(bk, bv);
    mega2_kernel<<<512, 256, M2_SMEM>>>(h_prime, Wq, bq, Wg, bg, Wb, bb);
    final_kernel<<<FK_GRID, 256, FK_SMEM>>>(h_prime, We, out);
}